// round 1
// baseline (speedup 1.0000x reference)
#include <cuda_runtime.h>
#include <math.h>

// Problem constants (fixed by the reference: B=2,S=2048,H=1024,I=4096,E=8)
#define NTOK 4096
#define HDIM 1024
#define IDIM 4096
#define ENUM 8

// Scratch (no cudaMalloc allowed): hmid for ONE expert at a time (64 MB),
// plus sorted router weights (128 KB).
__device__ float g_hmid[(size_t)NTOK * IDIM];
__device__ float g_w[NTOK * ENUM];

// ---------------------------------------------------------------------------
// Router: logits = x @ Wr^T, softmax over 8 experts, sort probs DESCENDING
// (reference uses top_k with k==E: expert e's output is weighted by the e-th
//  LARGEST prob, not the prob of expert e).
// One warp per token.
// ---------------------------------------------------------------------------
__global__ void router_kernel(const float* __restrict__ x,
                              const float* __restrict__ Wr,
                              float* __restrict__ wout) {
    int warp = (blockIdx.x * blockDim.x + threadIdx.x) >> 5;
    int lane = threadIdx.x & 31;
    if (warp >= NTOK) return;
    const float* xr = x + (size_t)warp * HDIM;

    float acc[ENUM];
#pragma unroll
    for (int e = 0; e < ENUM; e++) acc[e] = 0.f;

    for (int h = lane; h < HDIM; h += 32) {
        float xv = xr[h];
#pragma unroll
        for (int e = 0; e < ENUM; e++) acc[e] += xv * Wr[e * HDIM + h];
    }
#pragma unroll
    for (int e = 0; e < ENUM; e++) {
#pragma unroll
        for (int off = 16; off > 0; off >>= 1)
            acc[e] += __shfl_xor_sync(0xffffffffu, acc[e], off);
    }
    if (lane == 0) {
        float mx = acc[0];
#pragma unroll
        for (int e = 1; e < ENUM; e++) mx = fmaxf(mx, acc[e]);
        float s = 0.f;
#pragma unroll
        for (int e = 0; e < ENUM; e++) { acc[e] = expf(acc[e] - mx); s += acc[e]; }
        float inv = 1.f / s;
#pragma unroll
        for (int e = 0; e < ENUM; e++) acc[e] *= inv;

        // Batcher odd-even sorting network for 8, descending (static indices
        // -> stays in registers).
#define CE_DESC(a, b) { float _hi = fmaxf(a, b), _lo = fminf(a, b); (a) = _hi; (b) = _lo; }
        CE_DESC(acc[0], acc[1]); CE_DESC(acc[2], acc[3]);
        CE_DESC(acc[4], acc[5]); CE_DESC(acc[6], acc[7]);
        CE_DESC(acc[0], acc[2]); CE_DESC(acc[1], acc[3]);
        CE_DESC(acc[4], acc[6]); CE_DESC(acc[5], acc[7]);
        CE_DESC(acc[1], acc[2]); CE_DESC(acc[5], acc[6]);
        CE_DESC(acc[0], acc[4]); CE_DESC(acc[1], acc[5]);
        CE_DESC(acc[2], acc[6]); CE_DESC(acc[3], acc[7]);
        CE_DESC(acc[2], acc[4]); CE_DESC(acc[3], acc[5]);
        CE_DESC(acc[1], acc[2]); CE_DESC(acc[3], acc[4]); CE_DESC(acc[5], acc[6]);
#undef CE_DESC

#pragma unroll
        for (int e = 0; e < ENUM; e++) wout[warp * ENUM + e] = acc[e];
    }
}

// ---------------------------------------------------------------------------
// NT GEMM: C[m,n] = sum_k A[m*K+k] * B[n*K+k]   (both operands K-contiguous)
// BM=BN=128, BK=8, 256 threads, 8x8 per thread.
// DO_GELU:  C = gelu_exact(acc)        (GEMM1: X @ W1e^T)
// else:     C = (e==0 ? 0 : C) + w[row*8+e]*acc   (GEMM2 + weighted combine)
// ---------------------------------------------------------------------------
template <bool DO_GELU>
__global__ __launch_bounds__(256, 2)
void gemm_nt_kernel(const float* __restrict__ A, const float* __restrict__ B,
                    float* __restrict__ C, int K, int N,
                    const float* __restrict__ w, int e) {
    __shared__ float As[8][128];
    __shared__ float Bs[8][128];

    const int tid  = threadIdx.x;
    const int tx   = tid & 15;        // 0..15 -> N within tile
    const int ty   = tid >> 4;        // 0..15 -> M within tile
    const int lrow = tid >> 1;        // 0..127 loader row
    const int lcol = (tid & 1) * 4;   // 0 or 4

    const float* Ap = A + (size_t)(blockIdx.y * 128 + lrow) * K + lcol;
    const float* Bp = B + (size_t)(blockIdx.x * 128 + lrow) * K + lcol;

    float acc[8][8];
#pragma unroll
    for (int i = 0; i < 8; i++)
#pragma unroll
        for (int j = 0; j < 8; j++) acc[i][j] = 0.f;

    for (int k0 = 0; k0 < K; k0 += 8) {
        float4 av = *(const float4*)(Ap + k0);
        float4 bv = *(const float4*)(Bp + k0);
        __syncthreads();  // previous tile fully consumed before overwrite
        As[lcol + 0][lrow] = av.x; As[lcol + 1][lrow] = av.y;
        As[lcol + 2][lrow] = av.z; As[lcol + 3][lrow] = av.w;
        Bs[lcol + 0][lrow] = bv.x; Bs[lcol + 1][lrow] = bv.y;
        Bs[lcol + 2][lrow] = bv.z; Bs[lcol + 3][lrow] = bv.w;
        __syncthreads();
#pragma unroll
        for (int kk = 0; kk < 8; kk++) {
            float ra[8], rb[8];
            *(float4*)&ra[0] = *(const float4*)&As[kk][ty * 8];
            *(float4*)&ra[4] = *(const float4*)&As[kk][ty * 8 + 4];
            *(float4*)&rb[0] = *(const float4*)&Bs[kk][tx * 8];
            *(float4*)&rb[4] = *(const float4*)&Bs[kk][tx * 8 + 4];
#pragma unroll
            for (int i = 0; i < 8; i++)
#pragma unroll
                for (int j = 0; j < 8; j++)
                    acc[i][j] = fmaf(ra[i], rb[j], acc[i][j]);
        }
    }

    const int crow0 = blockIdx.y * 128 + ty * 8;
    const int ccol0 = blockIdx.x * 128 + tx * 8;

    if (DO_GELU) {
#pragma unroll
        for (int i = 0; i < 8; i++) {
            float* Crow = C + (size_t)(crow0 + i) * N + ccol0;
            float out[8];
#pragma unroll
            for (int j = 0; j < 8; j++) {
                float v = acc[i][j];
                // exact erf GELU (torch nn.GELU default)
                out[j] = 0.5f * v * (1.0f + erff(v * 0.70710678118654752f));
            }
            *(float4*)&Crow[0] = *(const float4*)&out[0];
            *(float4*)&Crow[4] = *(const float4*)&out[4];
        }
    } else {
#pragma unroll
        for (int i = 0; i < 8; i++) {
            const int row = crow0 + i;
            const float scale = w[row * ENUM + e];
            float* Crow = C + (size_t)row * N + ccol0;
            float out[8];
            if (e == 0) {
#pragma unroll
                for (int j = 0; j < 8; j++) out[j] = scale * acc[i][j];
            } else {
                float4 c0 = *(const float4*)&Crow[0];
                float4 c1 = *(const float4*)&Crow[4];
                out[0] = c0.x + scale * acc[i][0];
                out[1] = c0.y + scale * acc[i][1];
                out[2] = c0.z + scale * acc[i][2];
                out[3] = c0.w + scale * acc[i][3];
                out[4] = c1.x + scale * acc[i][4];
                out[5] = c1.y + scale * acc[i][5];
                out[6] = c1.z + scale * acc[i][6];
                out[7] = c1.w + scale * acc[i][7];
            }
            *(float4*)&Crow[0] = *(const float4*)&out[0];
            *(float4*)&Crow[4] = *(const float4*)&out[4];
        }
    }
}

// ---------------------------------------------------------------------------
extern "C" void kernel_launch(void* const* d_in, const int* in_sizes, int n_in,
                              void* d_out, int out_size) {
    const float* x  = (const float*)d_in[0];  // (B,S,H) -> (4096, 1024)
    const float* Wr = (const float*)d_in[1];  // (E, H)
    const float* W1 = (const float*)d_in[2];  // (E, I, H)
    const float* W2 = (const float*)d_in[3];  // (E, H, I)
    float* out = (float*)d_out;               // (4096, 1024)

    float* hmid = nullptr;
    float* wbuf = nullptr;
    cudaGetSymbolAddress((void**)&hmid, g_hmid);
    cudaGetSymbolAddress((void**)&wbuf, g_w);

    // Router: 4096 warps
    router_kernel<<<(NTOK * 32) / 256, 256>>>(x, Wr, wbuf);

    for (int e = 0; e < ENUM; e++) {
        const float* W1e = W1 + (size_t)e * IDIM * HDIM;
        const float* W2e = W2 + (size_t)e * HDIM * IDIM;

        // GEMM1: hmid(4096 x 4096) = gelu(X @ W1e^T), K=1024
        {
            dim3 grid(IDIM / 128, NTOK / 128);  // (32, 32)
            gemm_nt_kernel<true><<<grid, 256>>>(x, W1e, hmid, HDIM, IDIM,
                                                nullptr, e);
        }
        // GEMM2: out(4096 x 1024) (+)= w[:,e] * (hmid @ W2e^T), K=4096
        {
            dim3 grid(HDIM / 128, NTOK / 128);  // (8, 32)
            gemm_nt_kernel<false><<<grid, 256>>>(hmid, W2e, out, IDIM, HDIM,
                                                 wbuf, e);
        }
    }
}

// round 5
// speedup vs baseline: 3.0851x; 3.0851x over previous
#include <cuda_runtime.h>
#include <math.h>
#include <stdint.h>

// Problem constants (B=2,S=2048,H=1024,I=4096,E=8)
#define NTOK 4096
#define HDIM 1024
#define IDIM 4096
#define ENUM 8

// Scratch (no cudaMalloc): hmid for one expert (64MB) + router weights.
__device__ float g_hmid[(size_t)NTOK * IDIM];
__device__ float g_w[NTOK * ENUM];

// ---------------------------------------------------------------------------
// Router: logits = x @ Wr^T, softmax, sort DESC (top_k with k==E semantics).
// ---------------------------------------------------------------------------
__global__ void router_kernel(const float* __restrict__ x,
                              const float* __restrict__ Wr,
                              float* __restrict__ wout) {
    int warp = (blockIdx.x * blockDim.x + threadIdx.x) >> 5;
    int lane = threadIdx.x & 31;
    if (warp >= NTOK) return;
    const float* xr = x + (size_t)warp * HDIM;

    float acc[ENUM];
#pragma unroll
    for (int e = 0; e < ENUM; e++) acc[e] = 0.f;
    for (int h = lane; h < HDIM; h += 32) {
        float xv = xr[h];
#pragma unroll
        for (int e = 0; e < ENUM; e++) acc[e] += xv * Wr[e * HDIM + h];
    }
#pragma unroll
    for (int e = 0; e < ENUM; e++) {
#pragma unroll
        for (int off = 16; off > 0; off >>= 1)
            acc[e] += __shfl_xor_sync(0xffffffffu, acc[e], off);
    }
    if (lane == 0) {
        float mx = acc[0];
#pragma unroll
        for (int e = 1; e < ENUM; e++) mx = fmaxf(mx, acc[e]);
        float s = 0.f;
#pragma unroll
        for (int e = 0; e < ENUM; e++) { acc[e] = expf(acc[e] - mx); s += acc[e]; }
        float inv = 1.f / s;
#pragma unroll
        for (int e = 0; e < ENUM; e++) acc[e] *= inv;
#define CE_DESC(a, b) { float _hi = fmaxf(a, b), _lo = fminf(a, b); (a) = _hi; (b) = _lo; }
        CE_DESC(acc[0], acc[1]); CE_DESC(acc[2], acc[3]);
        CE_DESC(acc[4], acc[5]); CE_DESC(acc[6], acc[7]);
        CE_DESC(acc[0], acc[2]); CE_DESC(acc[1], acc[3]);
        CE_DESC(acc[4], acc[6]); CE_DESC(acc[5], acc[7]);
        CE_DESC(acc[1], acc[2]); CE_DESC(acc[5], acc[6]);
        CE_DESC(acc[0], acc[4]); CE_DESC(acc[1], acc[5]);
        CE_DESC(acc[2], acc[6]); CE_DESC(acc[3], acc[7]);
        CE_DESC(acc[2], acc[4]); CE_DESC(acc[3], acc[5]);
        CE_DESC(acc[1], acc[2]); CE_DESC(acc[3], acc[4]); CE_DESC(acc[5], acc[6]);
#undef CE_DESC
#pragma unroll
        for (int e = 0; e < ENUM; e++) wout[warp * ENUM + e] = acc[e];
    }
}

// ---------------------------------------------------------------------------
// tf32 mma.sync helpers
// ---------------------------------------------------------------------------
__device__ __forceinline__ uint32_t f2tf32(float f) {
    uint32_t r;
    asm("cvt.rna.tf32.f32 %0, %1;" : "=r"(r) : "f"(f));
    return r;
}

__device__ __forceinline__ void mma_tf32(float& c0, float& c1, float& c2, float& c3,
                                         uint32_t a0, uint32_t a1, uint32_t a2, uint32_t a3,
                                         uint32_t b0, uint32_t b1) {
    asm volatile(
        "mma.sync.aligned.m16n8k8.row.col.f32.tf32.tf32.f32 "
        "{%0,%1,%2,%3}, {%4,%5,%6,%7}, {%8,%9}, {%0,%1,%2,%3};"
        : "+f"(c0), "+f"(c1), "+f"(c2), "+f"(c3)
        : "r"(a0), "r"(a1), "r"(a2), "r"(a3), "r"(b0), "r"(b1));
}

// ---------------------------------------------------------------------------
// tf32 NT GEMM: C[m,n] = op( sum_k A[m,k]*B[n,k] ), A,B K-contiguous.
// BM=BN=128, BK=32, 256 threads (8 warps: 4 M x 2 N, warp tile 32x64).
// Double-buffered padded SMEM; tf32 conversion (cvt.rna) at SMEM-store time.
// DO_GELU: C = gelu_exact(acc);  else: C (+)= w[row*8+e] * acc
// ---------------------------------------------------------------------------
#define BK 32
#define LDS_PITCH 36  // 32 + 4 pad floats -> conflict-free frag loads
#define TILE_FLOATS (128 * LDS_PITCH)
#define SMEM_BYTES (4 * TILE_FLOATS * 4 * 2 / 2)  // 2 stages * (A+B) * 18432B = 73728

template <bool DO_GELU>
__global__ __launch_bounds__(256)
void tf32_gemm_kernel(const float* __restrict__ A, const float* __restrict__ B,
                      float* __restrict__ C, int K, int N,
                      const float* __restrict__ w, int e) {
    extern __shared__ float smem[];
    // layout: As[2][128][36] at 0, Bs[2][128][36] at 2*TILE_FLOATS
    float* As = smem;
    float* Bs = smem + 2 * TILE_FLOATS;

    const int tid = threadIdx.x;
    const int wid = tid >> 5;
    const int lid = tid & 31;
    const int lq = lid >> 2;   // 0..7
    const int lr = lid & 3;    // 0..3

    const int wm = wid >> 1;   // 0..3 -> M
    const int wn = wid & 1;    // 0..1 -> N
    const int m0 = wm * 32;
    const int n0 = wn * 64;

    const int mrow0 = blockIdx.y * 128;
    const int ncol0 = blockIdx.x * 128;
    const int nchunks = K >> 5;

    const float* Abase = A + (size_t)mrow0 * K;
    const float* Bbase = B + (size_t)ncol0 * K;

    // loader map: 4 float4 per tile per thread
    const int f4r[4] = { (tid + 0) >> 3, (tid + 256) >> 3, (tid + 512) >> 3, (tid + 768) >> 3 };
    const int f4c = (tid & 7) * 4;  // float offset within 32-float chunk row

    float acc[64];
#pragma unroll
    for (int i = 0; i < 64; i++) acc[i] = 0.f;

    float4 pa[4], pb[4];

    // preload chunk 0
#pragma unroll
    for (int i = 0; i < 4; i++) {
        pa[i] = *(const float4*)(Abase + (size_t)f4r[i] * K + f4c);
        pb[i] = *(const float4*)(Bbase + (size_t)f4r[i] * K + f4c);
    }
#pragma unroll
    for (int i = 0; i < 4; i++) {
        float* as = As + f4r[i] * LDS_PITCH + f4c;
        float* bs = Bs + f4r[i] * LDS_PITCH + f4c;
        as[0] = __uint_as_float(f2tf32(pa[i].x)); as[1] = __uint_as_float(f2tf32(pa[i].y));
        as[2] = __uint_as_float(f2tf32(pa[i].z)); as[3] = __uint_as_float(f2tf32(pa[i].w));
        bs[0] = __uint_as_float(f2tf32(pb[i].x)); bs[1] = __uint_as_float(f2tf32(pb[i].y));
        bs[2] = __uint_as_float(f2tf32(pb[i].z)); bs[3] = __uint_as_float(f2tf32(pb[i].w));
    }
    __syncthreads();

    for (int kc = 0; kc < nchunks; kc++) {
        // prefetch next chunk into registers
        if (kc + 1 < nchunks) {
            const float* An = Abase + (kc + 1) * BK;
            const float* Bn = Bbase + (kc + 1) * BK;
#pragma unroll
            for (int i = 0; i < 4; i++) {
                pa[i] = *(const float4*)(An + (size_t)f4r[i] * K + f4c);
                pb[i] = *(const float4*)(Bn + (size_t)f4r[i] * K + f4c);
            }
        }

        // compute from stage kc&1
        const float* as = As + (kc & 1) * TILE_FLOATS;
        const float* bs = Bs + (kc & 1) * TILE_FLOATS;
#pragma unroll
        for (int kk = 0; kk < 4; kk++) {
            const int k8 = kk * 8;
            uint32_t af[2][4], bf[8][2];
#pragma unroll
            for (int im = 0; im < 2; im++) {
                const int r = m0 + im * 16 + lq;
                af[im][0] = __float_as_uint(as[(r)     * LDS_PITCH + k8 + lr]);
                af[im][1] = __float_as_uint(as[(r + 8) * LDS_PITCH + k8 + lr]);
                af[im][2] = __float_as_uint(as[(r)     * LDS_PITCH + k8 + 4 + lr]);
                af[im][3] = __float_as_uint(as[(r + 8) * LDS_PITCH + k8 + 4 + lr]);
            }
#pragma unroll
            for (int in_ = 0; in_ < 8; in_++) {
                const int cn = n0 + in_ * 8 + lq;
                bf[in_][0] = __float_as_uint(bs[cn * LDS_PITCH + k8 + lr]);
                bf[in_][1] = __float_as_uint(bs[cn * LDS_PITCH + k8 + 4 + lr]);
            }
#pragma unroll
            for (int im = 0; im < 2; im++)
#pragma unroll
                for (int in_ = 0; in_ < 8; in_++) {
                    float* c = &acc[(im * 8 + in_) * 4];
                    mma_tf32(c[0], c[1], c[2], c[3],
                             af[im][0], af[im][1], af[im][2], af[im][3],
                             bf[in_][0], bf[in_][1]);
                }
        }

        // store prefetched chunk into stage (kc+1)&1
        if (kc + 1 < nchunks) {
            float* asn = As + ((kc + 1) & 1) * TILE_FLOATS;
            float* bsn = Bs + ((kc + 1) & 1) * TILE_FLOATS;
#pragma unroll
            for (int i = 0; i < 4; i++) {
                float* a4 = asn + f4r[i] * LDS_PITCH + f4c;
                float* b4 = bsn + f4r[i] * LDS_PITCH + f4c;
                a4[0] = __uint_as_float(f2tf32(pa[i].x)); a4[1] = __uint_as_float(f2tf32(pa[i].y));
                a4[2] = __uint_as_float(f2tf32(pa[i].z)); a4[3] = __uint_as_float(f2tf32(pa[i].w));
                b4[0] = __uint_as_float(f2tf32(pb[i].x)); b4[1] = __uint_as_float(f2tf32(pb[i].y));
                b4[2] = __uint_as_float(f2tf32(pb[i].z)); b4[3] = __uint_as_float(f2tf32(pb[i].w));
            }
        }
        __syncthreads();
    }

    // ---------------- epilogue ----------------
#pragma unroll
    for (int im = 0; im < 2; im++) {
        const int row_hi = mrow0 + m0 + im * 16 + lq;       // c0/c1 row
        const int row_lo = row_hi + 8;                      // c2/c3 row
        float s_hi = 0.f, s_lo = 0.f;
        if (!DO_GELU) {
            s_hi = w[row_hi * ENUM + e];
            s_lo = w[row_lo * ENUM + e];
        }
#pragma unroll
        for (int in_ = 0; in_ < 8; in_++) {
            const float* c = &acc[(im * 8 + in_) * 4];
            const int col = ncol0 + n0 + in_ * 8 + 2 * lr;
            float* p_hi = C + (size_t)row_hi * N + col;
            float* p_lo = C + (size_t)row_lo * N + col;
            if (DO_GELU) {
                float2 o_hi, o_lo;
                o_hi.x = 0.5f * c[0] * (1.0f + erff(c[0] * 0.70710678118654752f));
                o_hi.y = 0.5f * c[1] * (1.0f + erff(c[1] * 0.70710678118654752f));
                o_lo.x = 0.5f * c[2] * (1.0f + erff(c[2] * 0.70710678118654752f));
                o_lo.y = 0.5f * c[3] * (1.0f + erff(c[3] * 0.70710678118654752f));
                *(float2*)p_hi = o_hi;
                *(float2*)p_lo = o_lo;
            } else {
                float2 o_hi, o_lo;
                if (e == 0) {
                    o_hi = make_float2(s_hi * c[0], s_hi * c[1]);
                    o_lo = make_float2(s_lo * c[2], s_lo * c[3]);
                } else {
                    float2 d_hi = *(const float2*)p_hi;
                    float2 d_lo = *(const float2*)p_lo;
                    o_hi = make_float2(d_hi.x + s_hi * c[0], d_hi.y + s_hi * c[1]);
                    o_lo = make_float2(d_lo.x + s_lo * c[2], d_lo.y + s_lo * c[3]);
                }
                *(float2*)p_hi = o_hi;
                *(float2*)p_lo = o_lo;
            }
        }
    }
}

// ---------------------------------------------------------------------------
extern "C" void kernel_launch(void* const* d_in, const int* in_sizes, int n_in,
                              void* d_out, int out_size) {
    const float* x  = (const float*)d_in[0];  // (4096, 1024)
    const float* Wr = (const float*)d_in[1];  // (8, 1024)
    const float* W1 = (const float*)d_in[2];  // (8, 4096, 1024)
    const float* W2 = (const float*)d_in[3];  // (8, 1024, 4096)
    float* out = (float*)d_out;               // (4096, 1024)

    float* hmid = nullptr;
    float* wbuf = nullptr;
    cudaGetSymbolAddress((void**)&hmid, g_hmid);
    cudaGetSymbolAddress((void**)&wbuf, g_w);

    cudaFuncSetAttribute(tf32_gemm_kernel<true>,
                         cudaFuncAttributeMaxDynamicSharedMemorySize, SMEM_BYTES);
    cudaFuncSetAttribute(tf32_gemm_kernel<false>,
                         cudaFuncAttributeMaxDynamicSharedMemorySize, SMEM_BYTES);

    router_kernel<<<(NTOK * 32) / 256, 256>>>(x, Wr, wbuf);

    for (int e = 0; e < ENUM; e++) {
        const float* W1e = W1 + (size_t)e * IDIM * HDIM;
        const float* W2e = W2 + (size_t)e * HDIM * IDIM;

        // GEMM1: hmid(4096x4096) = gelu(X @ W1e^T), K=1024
        {
            dim3 grid(IDIM / 128, NTOK / 128);  // (32, 32)
            tf32_gemm_kernel<true><<<grid, 256, SMEM_BYTES>>>(
                x, W1e, hmid, HDIM, IDIM, nullptr, e);
        }
        // GEMM2: out(4096x1024) (+)= w[:,e] * (hmid @ W2e^T), K=4096
        {
            dim3 grid(HDIM / 128, NTOK / 128);  // (8, 32)
            tf32_gemm_kernel<false><<<grid, 256, SMEM_BYTES>>>(
                hmid, W2e, out, IDIM, HDIM, wbuf, e);
        }
    }
}

// round 7
// speedup vs baseline: 3.8830x; 1.2586x over previous
#include <cuda_runtime.h>
#include <math.h>
#include <stdint.h>

// Problem constants (B=2,S=2048,H=1024,I=4096,E=8)
#define NTOK 4096
#define HDIM 1024
#define IDIM 4096
#define ENUM 8

// Scratch (no cudaMalloc): tf32-preconverted operands + hmid + router weights.
__device__ float g_x32[(size_t)NTOK * HDIM];           // 16 MB
__device__ float g_w1t[(size_t)ENUM * IDIM * HDIM];    // 128 MB
__device__ float g_w2t[(size_t)ENUM * HDIM * IDIM];    // 128 MB
__device__ float g_hmid[(size_t)NTOK * IDIM];          // 64 MB (tf32 bits)
__device__ float g_w[NTOK * ENUM];

// ---------------------------------------------------------------------------
// helpers
// ---------------------------------------------------------------------------
__device__ __forceinline__ uint32_t f2tf32(float f) {
    uint32_t r;
    asm("cvt.rna.tf32.f32 %0, %1;" : "=r"(r) : "f"(f));
    return r;
}
__device__ __forceinline__ uint32_t smem_u32(const void* p) {
    uint32_t a;
    asm("{ .reg .u64 t; cvta.to.shared.u64 t, %1; cvt.u32.u64 %0, t; }"
        : "=r"(a) : "l"(p));
    return a;
}
__device__ __forceinline__ void cp_async16(uint32_t s, const void* g) {
    asm volatile("cp.async.ca.shared.global [%0], [%1], 16;" :: "r"(s), "l"(g));
}
#define CP_COMMIT() asm volatile("cp.async.commit_group;" ::: "memory")
#define CP_WAIT0()  asm volatile("cp.async.wait_group 0;" ::: "memory")

__device__ __forceinline__ void mma_tf32(float& c0, float& c1, float& c2, float& c3,
                                         uint32_t a0, uint32_t a1, uint32_t a2, uint32_t a3,
                                         uint32_t b0, uint32_t b1) {
    asm volatile(
        "mma.sync.aligned.m16n8k8.row.col.f32.tf32.tf32.f32 "
        "{%0,%1,%2,%3}, {%4,%5,%6,%7}, {%8,%9}, {%0,%1,%2,%3};"
        : "+f"(c0), "+f"(c1), "+f"(c2), "+f"(c3)
        : "r"(a0), "r"(a1), "r"(a2), "r"(a3), "r"(b0), "r"(b1));
}

// ---------------------------------------------------------------------------
// tf32 pre-conversion: dst = tf32_rna(src), vectorized
// ---------------------------------------------------------------------------
__global__ void convert_tf32_kernel(const float* __restrict__ src,
                                    float* __restrict__ dst, int n4) {
    int i = blockIdx.x * blockDim.x + threadIdx.x;
    int stride = gridDim.x * blockDim.x;
    for (; i < n4; i += stride) {
        float4 v = ((const float4*)src)[i];
        v.x = __uint_as_float(f2tf32(v.x));
        v.y = __uint_as_float(f2tf32(v.y));
        v.z = __uint_as_float(f2tf32(v.z));
        v.w = __uint_as_float(f2tf32(v.w));
        ((float4*)dst)[i] = v;
    }
}

// ---------------------------------------------------------------------------
// Router: logits = x @ Wr^T, softmax, sort DESC (top_k with k==E semantics).
// ---------------------------------------------------------------------------
__global__ void router_kernel(const float* __restrict__ x,
                              const float* __restrict__ Wr,
                              float* __restrict__ wout) {
    int warp = (blockIdx.x * blockDim.x + threadIdx.x) >> 5;
    int lane = threadIdx.x & 31;
    if (warp >= NTOK) return;
    const float* xr = x + (size_t)warp * HDIM;

    float acc[ENUM];
#pragma unroll
    for (int e = 0; e < ENUM; e++) acc[e] = 0.f;
    for (int h = lane; h < HDIM; h += 32) {
        float xv = xr[h];
#pragma unroll
        for (int e = 0; e < ENUM; e++) acc[e] += xv * Wr[e * HDIM + h];
    }
#pragma unroll
    for (int e = 0; e < ENUM; e++) {
#pragma unroll
        for (int off = 16; off > 0; off >>= 1)
            acc[e] += __shfl_xor_sync(0xffffffffu, acc[e], off);
    }
    if (lane == 0) {
        float mx = acc[0];
#pragma unroll
        for (int e = 1; e < ENUM; e++) mx = fmaxf(mx, acc[e]);
        float s = 0.f;
#pragma unroll
        for (int e = 0; e < ENUM; e++) { acc[e] = expf(acc[e] - mx); s += acc[e]; }
        float inv = 1.f / s;
#pragma unroll
        for (int e = 0; e < ENUM; e++) acc[e] *= inv;
#define CE_DESC(a, b) { float _hi = fmaxf(a, b), _lo = fminf(a, b); (a) = _hi; (b) = _lo; }
        CE_DESC(acc[0], acc[1]); CE_DESC(acc[2], acc[3]);
        CE_DESC(acc[4], acc[5]); CE_DESC(acc[6], acc[7]);
        CE_DESC(acc[0], acc[2]); CE_DESC(acc[1], acc[3]);
        CE_DESC(acc[4], acc[6]); CE_DESC(acc[5], acc[7]);
        CE_DESC(acc[1], acc[2]); CE_DESC(acc[5], acc[6]);
        CE_DESC(acc[0], acc[4]); CE_DESC(acc[1], acc[5]);
        CE_DESC(acc[2], acc[6]); CE_DESC(acc[3], acc[7]);
        CE_DESC(acc[2], acc[4]); CE_DESC(acc[3], acc[5]);
        CE_DESC(acc[1], acc[2]); CE_DESC(acc[3], acc[4]); CE_DESC(acc[5], acc[6]);
#undef CE_DESC
#pragma unroll
        for (int e = 0; e < ENUM; e++) wout[warp * ENUM + e] = acc[e];
    }
}

// ---------------------------------------------------------------------------
// tf32 NT GEMM: C[m,n] = op( sum_k A[m,k]*B[n,k] ); A,B already tf32 bits.
// BM=BN=128, BK=32, 256 threads (8 warps: 4Mx2N, warp tile 32x64).
// cp.async double-buffered SMEM, 2 CTAs/SM.
// DO_GELU: C = tf32(gelu_exact(acc));  else: C (+)= w[row*8+e]*acc
// ---------------------------------------------------------------------------
#define BK 32
#define LDS_PITCH 36
#define TILE_FLOATS (128 * LDS_PITCH)
#define SMEM_BYTES (4 * TILE_FLOATS * 4)  // 2 stages * (A+B): 73728 B

template <bool DO_GELU>
__global__ __launch_bounds__(256, 2)
void tf32_gemm_kernel(const float* __restrict__ A, const float* __restrict__ B,
                      float* __restrict__ C, int K, int N,
                      const float* __restrict__ w, int e) {
    extern __shared__ float smem[];
    float* As = smem;                    // [2][128][36]
    float* Bs = smem + 2 * TILE_FLOATS;  // [2][128][36]

    const int tid = threadIdx.x;
    const int wid = tid >> 5;
    const int lid = tid & 31;
    const int lq = lid >> 2;  // 0..7
    const int lr = lid & 3;   // 0..3

    const int m0 = (wid >> 1) * 32;
    const int n0 = (wid & 1) * 64;

    const int mrow0 = blockIdx.y * 128;
    const int ncol0 = blockIdx.x * 128;
    const int nchunks = K >> 5;

    const float* Abase = A + (size_t)mrow0 * K;
    const float* Bbase = B + (size_t)ncol0 * K;

    const int f4row = tid >> 3;        // 0..31
    const int f4c = (tid & 7) * 4;     // float col within 32-float chunk

    const uint32_t as_u = smem_u32(As);
    const uint32_t bs_u = smem_u32(Bs);

    float acc[64];
#pragma unroll
    for (int i = 0; i < 64; i++) acc[i] = 0.f;

    // issue stage st loads for chunk kc
    auto issue = [&](int kc, int st) {
        const float* Ak = Abase + kc * BK;
        const float* Bk = Bbase + kc * BK;
        const uint32_t a_s = as_u + (uint32_t)(st * TILE_FLOATS) * 4u;
        const uint32_t b_s = bs_u + (uint32_t)(st * TILE_FLOATS) * 4u;
#pragma unroll
        for (int i = 0; i < 4; i++) {
            const int row = f4row + i * 32;
            const uint32_t so = (uint32_t)(row * LDS_PITCH + f4c) * 4u;
            cp_async16(a_s + so, Ak + (size_t)row * K + f4c);
            cp_async16(b_s + so, Bk + (size_t)row * K + f4c);
        }
    };

    issue(0, 0);
    CP_COMMIT();

    for (int kc = 0; kc < nchunks; kc++) {
        CP_WAIT0();
        __syncthreads();  // stage kc visible CTA-wide; all done with kc-1 compute
        if (kc + 1 < nchunks) {
            issue(kc + 1, (kc + 1) & 1);
            CP_COMMIT();
        }

        const float* as = As + (kc & 1) * TILE_FLOATS;
        const float* bs = Bs + (kc & 1) * TILE_FLOATS;
#pragma unroll
        for (int kk = 0; kk < 4; kk++) {
            const int k8 = kk * 8;
            uint32_t af[2][4], bf[8][2];
#pragma unroll
            for (int im = 0; im < 2; im++) {
                const int r = m0 + im * 16 + lq;
                af[im][0] = __float_as_uint(as[(r)     * LDS_PITCH + k8 + lr]);
                af[im][1] = __float_as_uint(as[(r + 8) * LDS_PITCH + k8 + lr]);
                af[im][2] = __float_as_uint(as[(r)     * LDS_PITCH + k8 + 4 + lr]);
                af[im][3] = __float_as_uint(as[(r + 8) * LDS_PITCH + k8 + 4 + lr]);
            }
#pragma unroll
            for (int in_ = 0; in_ < 8; in_++) {
                const int cn = n0 + in_ * 8 + lq;
                bf[in_][0] = __float_as_uint(bs[cn * LDS_PITCH + k8 + lr]);
                bf[in_][1] = __float_as_uint(bs[cn * LDS_PITCH + k8 + 4 + lr]);
            }
#pragma unroll
            for (int im = 0; im < 2; im++)
#pragma unroll
                for (int in_ = 0; in_ < 8; in_++) {
                    float* c = &acc[(im * 8 + in_) * 4];
                    mma_tf32(c[0], c[1], c[2], c[3],
                             af[im][0], af[im][1], af[im][2], af[im][3],
                             bf[in_][0], bf[in_][1]);
                }
        }
    }

    // ---------------- epilogue ----------------
#pragma unroll
    for (int im = 0; im < 2; im++) {
        const int row_hi = mrow0 + m0 + im * 16 + lq;
        const int row_lo = row_hi + 8;
        float s_hi = 0.f, s_lo = 0.f;
        if (!DO_GELU) {
            s_hi = w[row_hi * ENUM + e];
            s_lo = w[row_lo * ENUM + e];
        }
#pragma unroll
        for (int in_ = 0; in_ < 8; in_++) {
            const float* c = &acc[(im * 8 + in_) * 4];
            const int col = ncol0 + n0 + in_ * 8 + 2 * lr;
            float* p_hi = C + (size_t)row_hi * N + col;
            float* p_lo = C + (size_t)row_lo * N + col;
            if (DO_GELU) {
                // gelu then tf32-round (hmid feeds GEMM2's A operand directly)
                float g0 = 0.5f * c[0] * (1.0f + erff(c[0] * 0.70710678118654752f));
                float g1 = 0.5f * c[1] * (1.0f + erff(c[1] * 0.70710678118654752f));
                float g2 = 0.5f * c[2] * (1.0f + erff(c[2] * 0.70710678118654752f));
                float g3 = 0.5f * c[3] * (1.0f + erff(c[3] * 0.70710678118654752f));
                *(float2*)p_hi = make_float2(__uint_as_float(f2tf32(g0)),
                                             __uint_as_float(f2tf32(g1)));
                *(float2*)p_lo = make_float2(__uint_as_float(f2tf32(g2)),
                                             __uint_as_float(f2tf32(g3)));
            } else {
                float2 o_hi, o_lo;
                if (e == 0) {
                    o_hi = make_float2(s_hi * c[0], s_hi * c[1]);
                    o_lo = make_float2(s_lo * c[2], s_lo * c[3]);
                } else {
                    float2 d_hi = *(const float2*)p_hi;
                    float2 d_lo = *(const float2*)p_lo;
                    o_hi = make_float2(d_hi.x + s_hi * c[0], d_hi.y + s_hi * c[1]);
                    o_lo = make_float2(d_lo.x + s_lo * c[2], d_lo.y + s_lo * c[3]);
                }
                *(float2*)p_hi = o_hi;
                *(float2*)p_lo = o_lo;
            }
        }
    }
}

// ---------------------------------------------------------------------------
extern "C" void kernel_launch(void* const* d_in, const int* in_sizes, int n_in,
                              void* d_out, int out_size) {
    const float* x  = (const float*)d_in[0];  // (4096, 1024)
    const float* Wr = (const float*)d_in[1];  // (8, 1024)
    const float* W1 = (const float*)d_in[2];  // (8, 4096, 1024)
    const float* W2 = (const float*)d_in[3];  // (8, 1024, 4096)
    float* out = (float*)d_out;               // (4096, 1024)

    float *x32, *w1t, *w2t, *hmid, *wbuf;
    cudaGetSymbolAddress((void**)&x32, g_x32);
    cudaGetSymbolAddress((void**)&w1t, g_w1t);
    cudaGetSymbolAddress((void**)&w2t, g_w2t);
    cudaGetSymbolAddress((void**)&hmid, g_hmid);
    cudaGetSymbolAddress((void**)&wbuf, g_w);

    cudaFuncSetAttribute(tf32_gemm_kernel<true>,
                         cudaFuncAttributeMaxDynamicSharedMemorySize, SMEM_BYTES);
    cudaFuncSetAttribute(tf32_gemm_kernel<false>,
                         cudaFuncAttributeMaxDynamicSharedMemorySize, SMEM_BYTES);

    // Router (reads raw fp32 x)
    router_kernel<<<(NTOK * 32) / 256, 256>>>(x, Wr, wbuf);

    // tf32 pre-conversion of x, W1, W2
    convert_tf32_kernel<<<1184, 256>>>(x, x32, NTOK * HDIM / 4);
    convert_tf32_kernel<<<2368, 256>>>(W1, w1t, ENUM * IDIM * HDIM / 4);
    convert_tf32_kernel<<<2368, 256>>>(W2, w2t, ENUM * HDIM * IDIM / 4);

    for (int e = 0; e < ENUM; e++) {
        const float* W1e = w1t + (size_t)e * IDIM * HDIM;
        const float* W2e = w2t + (size_t)e * HDIM * IDIM;

        // GEMM1: hmid(4096x4096) = tf32(gelu(X @ W1e^T)), K=1024
        {
            dim3 grid(IDIM / 128, NTOK / 128);  // (32, 32)
            tf32_gemm_kernel<true><<<grid, 256, SMEM_BYTES>>>(
                x32, W1e, hmid, HDIM, IDIM, nullptr, e);
        }
        // GEMM2: out(4096x1024) (+)= w[:,e] * (hmid @ W2e^T), K=4096
        {
            dim3 grid(HDIM / 128, NTOK / 128);  // (8, 32)
            tf32_gemm_kernel<false><<<grid, 256, SMEM_BYTES>>>(
                hmid, W2e, out, IDIM, HDIM, wbuf, e);
        }
    }
}